// round 6
// baseline (speedup 1.0000x reference)
#include <cuda_runtime.h>
#include <cstdint>

// Problem constants
#define B_    4
#define T_    2048
#define C_DIM 1024
#define H_    16
#define D_    64
#define M_ROWS (B_*T_)      // 8192
#define QKV_N  (3*C_DIM)    // 3072
#define NEG_BIG (-3.0e38f)

// Scratch (device globals)
__device__ float g_q[8388608];    // [B,H,T,D]  tf32-prerounded (Q pre-scaled by 1/8)
__device__ float g_k[8388608];
__device__ float g_v[8388608];
__device__ float g_y[8388608];    // fragment-major [M=8192][C=1024], tf32-prerounded
__device__ float g_xr[8388608];   // x, fragment-major A-layout, tf32-rounded
__device__ float g_war[3145728];  // w_attn, fragment-major B-layout, tf32-rounded
__device__ float g_wpr[1048576];  // w_proj, fragment-major B-layout, tf32-rounded

// ---------------------------------------------------------------------------
// Helpers
// ---------------------------------------------------------------------------
__device__ __forceinline__ uint32_t cvta_smem(const void* p) {
    uint32_t a;
    asm("{ .reg .u64 t; cvta.to.shared.u64 t, %1; cvt.u32.u64 %0, t; }"
        : "=r"(a) : "l"(p));
    return a;
}
__device__ __forceinline__ void cp_async16(uint32_t dst, const void* src) {
    asm volatile("cp.async.cg.shared.global [%0], [%1], 16;" :: "r"(dst), "l"(src));
}
__device__ __forceinline__ void cp_commit() { asm volatile("cp.async.commit_group;"); }
__device__ __forceinline__ void cp_wait0()  { asm volatile("cp.async.wait_group 0;"); }
__device__ __forceinline__ void cp_wait1()  { asm volatile("cp.async.wait_group 1;"); }
__device__ __forceinline__ void cp_wait2()  { asm volatile("cp.async.wait_group 2;"); }

__device__ __forceinline__ uint32_t tf32_rne(float x) {
    uint32_t y;
    asm("cvt.rna.tf32.f32 %0, %1;" : "=r"(y) : "f"(x));
    return y;
}
__device__ __forceinline__ void mma_tf32(float* d, const uint32_t* a, const uint32_t* b) {
    asm volatile(
        "mma.sync.aligned.m16n8k8.row.col.f32.tf32.tf32.f32 "
        "{%0,%1,%2,%3}, {%4,%5,%6,%7}, {%8,%9}, {%0,%1,%2,%3};"
        : "+f"(d[0]), "+f"(d[1]), "+f"(d[2]), "+f"(d[3])
        : "r"(a[0]), "r"(a[1]), "r"(a[2]), "r"(a[3]), "r"(b[0]), "r"(b[1]));
}

// ---------------------------------------------------------------------------
// Fragment-major layouts.
// A-layout (x, y): per (mb = m>>7, kt = k>>5) block of 4096 contiguous floats:
//   tile t = mtile*4 + ks  (mtile = (m>>4)&7, ks = (k>>3)&3), 128 floats each:
//   lane = (m&7)*4 + (k&3);  regs: [0]=(m%16<8,k%8<4) [1]=+8rows [2]=+4cols [3]=both
// B-layout (weights): per (nb = n>>7, kt = k>>5) block of 4096 floats:
//   tile t = ntile*2 + kp   (ntile = (n>>3)&15, kp = (k>>4)&1), 128 floats each:
//   lane = (n&7)*4 + (k&3); regs: [0]=k0 [1]=k0+4 [2]=k0+8 [3]=k0+12, k0 = kp*16+qc
// ---------------------------------------------------------------------------
__global__ void __launch_bounds__(256) permA_kernel(
    const float* __restrict__ in, float* __restrict__ out, int K)
{
    __shared__ float t[128][33];
    const int kt = blockIdx.x, mb = blockIdx.y;
    const int tid = threadIdx.x;
    const int nkt = K >> 5;
    const float* src = in + (size_t)mb * 128 * K + kt * 32;
    #pragma unroll
    for (int i = 0; i < 4; ++i) {
        const int row = (tid >> 3) + i * 32;
        const int c4  = (tid & 7) * 4;
        float4 v = *(const float4*)(src + (size_t)row * K + c4);
        t[row][c4] = v.x; t[row][c4+1] = v.y; t[row][c4+2] = v.z; t[row][c4+3] = v.w;
    }
    __syncthreads();
    float* dst = out + (size_t)(mb * nkt + kt) * 4096;
    #pragma unroll
    for (int i = 0; i < 4; ++i) {
        const int f = tid + i * 256;          // float4 slot 0..1023
        const int tile = f >> 5, lane = f & 31;
        const int mtile = tile >> 2, ks = tile & 3;
        const int qr = lane >> 2, qc = lane & 3;
        const int m0 = mtile * 16 + qr, k0 = ks * 8 + qc;
        uint4 u;
        u.x = tf32_rne(t[m0][k0]);
        u.y = tf32_rne(t[m0 + 8][k0]);
        u.z = tf32_rne(t[m0][k0 + 4]);
        u.w = tf32_rne(t[m0 + 8][k0 + 4]);
        *(uint4*)(dst + f * 4) = u;
    }
}

__global__ void __launch_bounds__(256) permB_kernel(
    const float* __restrict__ in, float* __restrict__ out, int K)
{
    __shared__ float t[128][33];
    const int kt = blockIdx.x, nb = blockIdx.y;
    const int tid = threadIdx.x;
    const int nkt = K >> 5;
    const float* src = in + (size_t)nb * 128 * K + kt * 32;
    #pragma unroll
    for (int i = 0; i < 4; ++i) {
        const int row = (tid >> 3) + i * 32;
        const int c4  = (tid & 7) * 4;
        float4 v = *(const float4*)(src + (size_t)row * K + c4);
        t[row][c4] = v.x; t[row][c4+1] = v.y; t[row][c4+2] = v.z; t[row][c4+3] = v.w;
    }
    __syncthreads();
    float* dst = out + (size_t)(nb * nkt + kt) * 4096;
    #pragma unroll
    for (int i = 0; i < 4; ++i) {
        const int f = tid + i * 256;
        const int tile = f >> 5, lane = f & 31;
        const int ntile = tile >> 1, kp = tile & 1;
        const int qr = lane >> 2, qc = lane & 3;
        const int n0 = ntile * 8 + qr, k0 = kp * 16 + qc;
        uint4 u;
        u.x = tf32_rne(t[n0][k0]);
        u.y = tf32_rne(t[n0][k0 + 4]);
        u.z = tf32_rne(t[n0][k0 + 8]);
        u.w = tf32_rne(t[n0][k0 + 12]);
        *(uint4*)(dst + f * 4) = u;
    }
}

// ---------------------------------------------------------------------------
// tf32 mma GEMM, fragment-major pre-rounded inputs, 3-stage cp.async pipeline.
// out[m,n] = sum_k A[m,k]*W[n,k] + bias[n].  Block 128x128x32, 8 warps (2x4).
// Per stage: A 4096 + B 4096 floats (32KB), linear block copy.
// MODE 0: fp32 store to out[m*N+n]. MODE 1: tf32 scatter to g_q/g_k/g_v.
// ---------------------------------------------------------------------------
#define NSTAGE 3
#define STG_FLOATS 8192
#define GEMM_SMEM (NSTAGE * STG_FLOATS * (int)sizeof(float))   // 98304

template<int MODE>
__global__ void __launch_bounds__(256) gemm_mma_kernel(
    const float* __restrict__ A, const float* __restrict__ W,
    const float* __restrict__ bias, float* __restrict__ out,
    int N, int K)
{
    extern __shared__ float sm[];
    const int tid  = threadIdx.x;
    const int lane = tid & 31;
    const int wid  = tid >> 5;
    const int wm   = wid & 1;
    const int wn   = wid >> 1;
    const int qr   = lane >> 2;
    const int qc   = lane & 3;

    const int nkt = K >> 5;
    const int mb = blockIdx.y, nb = blockIdx.x;
    const float* Ablk = A + (size_t)mb * nkt * 4096;
    const float* Wblk = W + (size_t)nb * nkt * 4096;

    const uint32_t smem_base = cvta_smem(sm);

    float acc[4][4][4];
    #pragma unroll
    for (int i = 0; i < 4; ++i)
        #pragma unroll
        for (int j = 0; j < 4; ++j)
            #pragma unroll
            for (int r = 0; r < 4; ++r) acc[i][j][r] = 0.f;

    // Prologue: stages 0,1
    #pragma unroll
    for (int s = 0; s < 2; ++s) {
        const uint32_t dst = smem_base + (s * STG_FLOATS + tid * 16) * 4;
        const float* sa = Ablk + (size_t)s * 4096 + tid * 16;
        const float* sb = Wblk + (size_t)s * 4096 + tid * 16;
        #pragma unroll
        for (int j = 0; j < 4; ++j) {
            cp_async16(dst + j * 16,              sa + j * 4);
            cp_async16(dst + 4096 * 4 + j * 16,   sb + j * 4);
        }
        cp_commit();
    }

    for (int kt = 0; kt < nkt; ++kt) {
        __syncthreads();   // all warps done with stage (kt-1)%3 before overwrite
        if (kt + 2 < nkt) {
            const int s = (kt + 2) % NSTAGE;
            const uint32_t dst = smem_base + (s * STG_FLOATS + tid * 16) * 4;
            const float* sa = Ablk + (size_t)(kt + 2) * 4096 + tid * 16;
            const float* sb = Wblk + (size_t)(kt + 2) * 4096 + tid * 16;
            #pragma unroll
            for (int j = 0; j < 4; ++j) {
                cp_async16(dst + j * 16,            sa + j * 4);
                cp_async16(dst + 4096 * 4 + j * 16, sb + j * 4);
            }
            cp_commit();
            cp_wait2();
        } else if (kt + 1 < nkt) {
            cp_wait1();
        } else {
            cp_wait0();
        }
        __syncthreads();

        const uint32_t* Af = (const uint32_t*)(sm + (kt % NSTAGE) * STG_FLOATS);
        const uint32_t* Bf = Af + 4096;

        uint32_t bq[4][4];
        #pragma unroll
        for (int ks = 0; ks < 4; ++ks) {
            uint32_t af[4][4];
            #pragma unroll
            for (int mt = 0; mt < 4; ++mt) {
                const int mtile = wm * 4 + mt;
                *(uint4*)af[mt] = *(const uint4*)(Af + (mtile * 4 + ks) * 128 + lane * 4);
            }
            if ((ks & 1) == 0) {
                #pragma unroll
                for (int nt = 0; nt < 4; ++nt) {
                    const int ntile = wn * 4 + nt;
                    *(uint4*)bq[nt] = *(const uint4*)(Bf + (ntile * 2 + (ks >> 1)) * 128 + lane * 4);
                }
            }
            #pragma unroll
            for (int mt = 0; mt < 4; ++mt)
                #pragma unroll
                for (int nt = 0; nt < 4; ++nt) {
                    uint32_t bf2[2] = { bq[nt][(ks & 1) * 2], bq[nt][(ks & 1) * 2 + 1] };
                    mma_tf32(acc[mt][nt], af[mt], bf2);
                }
        }
    }

    // Epilogue
    const int rowBase = mb * 128, colBase = nb * 128;
    #pragma unroll
    for (int nt = 0; nt < 4; ++nt) {
        const int n0 = colBase + wn * 32 + nt * 8 + qc * 2;
        const float b0 = bias[n0], b1 = bias[n0 + 1];
        #pragma unroll
        for (int mt = 0; mt < 4; ++mt) {
            const int m0 = rowBase + wm * 64 + mt * 16 + qr;
            float2 v0 = make_float2(acc[mt][nt][0] + b0, acc[mt][nt][1] + b1);
            float2 v1 = make_float2(acc[mt][nt][2] + b0, acc[mt][nt][3] + b1);
            if (MODE == 0) {
                *(float2*)(out + (size_t)m0 * N + n0)       = v0;
                *(float2*)(out + (size_t)(m0 + 8) * N + n0) = v1;
            } else {
                const int sector = n0 >> 10;          // 0=Q 1=K 2=V
                const int c  = n0 & 1023;
                const int hh = c >> 6, dd = c & 63;
                float* dst = (sector == 0) ? g_q : (sector == 1) ? g_k : g_v;
                const float qs = (sector == 0) ? 0.125f : 1.0f;
                uint2 u0, u1;
                u0.x = tf32_rne(v0.x * qs); u0.y = tf32_rne(v0.y * qs);
                u1.x = tf32_rne(v1.x * qs); u1.y = tf32_rne(v1.y * qs);
                const int bb0 = m0 >> 11, tt0 = m0 & 2047;
                *(uint2*)(dst + ((((size_t)bb0 * H_ + hh) * T_) + tt0) * D_ + dd) = u0;
                const int m1 = m0 + 8;
                const int bb1 = m1 >> 11, tt1 = m1 & 2047;
                *(uint2*)(dst + ((((size_t)bb1 * H_ + hh) * T_) + tt1) * D_ + dd) = u1;
            }
        }
    }
}

// ---------------------------------------------------------------------------
// Tensor-core flash attention, tf32 mma, double-buffered K/V via cp.async.
// CTA = (b, h, 128-query tile), 8 warps. Epilogue writes y in fragment-major
// A-layout (tf32-rounded) so gemm2's mainloop needs no cvt / padding.
// ---------------------------------------------------------------------------
#define QP 68
#define VP 72
#define KV_FLOATS (64*QP + 64*VP)
#define ATTN_SMEM ((128*QP + 128*QP + 2*KV_FLOATS) * (int)sizeof(float))  // 141312

__global__ void __launch_bounds__(256) attn_mma_kernel(float* __restrict__ Y)
{
    extern __shared__ float sm[];
    float* Qs = sm;                      // [128][QP]
    float* Ps = Qs + 128*QP;             // [128][QP]
    float* KV = Ps + 128*QP;             // 2 stages of (Ks[64][QP], Vs[64][VP])

    const int qt  = gridDim.x - 1 - blockIdx.x;
    const int bh  = blockIdx.y;
    const int b   = bh >> 4, h = bh & 15;
    const int tid = threadIdx.x;
    const int lane = tid & 31;
    const int w    = tid >> 5;
    const int qr   = lane >> 2;
    const int qc   = lane & 3;

    const float* Qg = g_q + ((size_t)bh * T_ + qt * 128) * D_;
    const float* Kg = g_k + (size_t)bh * T_ * D_;
    const float* Vg = g_v + (size_t)bh * T_ * D_;

    const uint32_t kv_u = cvta_smem(KV);

    // Load Q tile (tf32-prerounded, pre-scaled): raw copy
    #pragma unroll
    for (int t = 0; t < 8; ++t) {
        const int slot = tid + t * 256;
        const int r  = slot >> 4;
        const int d0 = (slot & 15) << 2;
        *(float4*)(Qs + r * QP + d0) = *(const float4*)(Qg + r * 64 + d0);
    }

    float m0 = NEG_BIG, m1 = NEG_BIG, l0 = 0.f, l1 = 0.f;
    float oacc[8][4];
    #pragma unroll
    for (int nt = 0; nt < 8; ++nt)
        #pragma unroll
        for (int r = 0; r < 4; ++r) oacc[nt][r] = 0.f;

    const int row0 = w * 16 + qr;
    const int jmax = 2 * qt + 1;

    // Prologue: issue KV tile 0 into stage 0
    {
        #pragma unroll
        for (int t = 0; t < 4; ++t) {
            const int slot = tid + t * 256;
            const int r  = slot >> 4;
            const int d0 = (slot & 15) << 2;
            cp_async16(kv_u + (r * QP + d0) * 4, Kg + r * 64 + d0);
            cp_async16(kv_u + (64*QP + r * VP + d0) * 4, Vg + r * 64 + d0);
        }
        cp_commit();
    }

    for (int j = 0; j <= jmax; ++j) {
        __syncthreads();   // all warps done computing tile j-1 (its stage gets reused)

        if (j + 1 <= jmax) {
            const uint32_t stg = kv_u + ((j + 1) & 1) * KV_FLOATS * 4;
            const float* Kgt = Kg + (size_t)(j + 1) * 64 * 64;
            const float* Vgt = Vg + (size_t)(j + 1) * 64 * 64;
            #pragma unroll
            for (int t = 0; t < 4; ++t) {
                const int slot = tid + t * 256;
                const int r  = slot >> 4;
                const int d0 = (slot & 15) << 2;
                cp_async16(stg + (r * QP + d0) * 4, Kgt + r * 64 + d0);
                cp_async16(stg + (64*QP + r * VP + d0) * 4, Vgt + r * 64 + d0);
            }
            cp_commit();
            cp_wait1();
        } else {
            cp_wait0();
        }
        __syncthreads();

        const float* Ks = KV + (j & 1) * KV_FLOATS;
        const float* Vs = Ks + 64*QP;

        int ntmax = 8;
        if (j == 2 * qt) {
            ntmax = 2 * w + 2; if (ntmax > 8) ntmax = 8;
        } else if (j == 2 * qt + 1) {
            ntmax = 2 * w - 6; if (ntmax < 0) ntmax = 0;
        }

        if (ntmax > 0) {
            // ---- S = Q K^T ----
            float sacc[8][4];
            #pragma unroll
            for (int nt = 0; nt < 8; ++nt)
                #pragma unroll
                for (int r = 0; r < 4; ++r) sacc[nt][r] = 0.f;

            #pragma unroll
            for (int kc = 0; kc < 8; ++kc) {
                uint32_t a[4];
                const uint32_t* qb = (const uint32_t*)(Qs + (w*16 + qr) * QP + kc*8 + qc);
                a[0] = qb[0];
                a[1] = qb[8 * QP];
                a[2] = qb[4];
                a[3] = qb[8 * QP + 4];
                #pragma unroll
                for (int nt = 0; nt < 8; ++nt) {
                    if (nt < ntmax) {
                        uint32_t bf[2];
                        const uint32_t* kb = (const uint32_t*)(Ks + (nt*8 + qr) * QP + kc*8 + qc);
                        bf[0] = kb[0];
                        bf[1] = kb[4];
                        mma_tf32(sacc[nt], a, bf);
                    }
                }
            }

            // ---- Causal mask (diagonal tiles) ----
            if (j >= 2 * qt) {
                const int rel = (j - 2 * qt) * 64;
                #pragma unroll
                for (int nt = 0; nt < 8; ++nt) {
                    if (nt < ntmax) {
                        const int col = rel + nt * 8 + qc * 2;
                        if (col     > row0)     sacc[nt][0] = NEG_BIG;
                        if (col + 1 > row0)     sacc[nt][1] = NEG_BIG;
                        if (col     > row0 + 8) sacc[nt][2] = NEG_BIG;
                        if (col + 1 > row0 + 8) sacc[nt][3] = NEG_BIG;
                    }
                }
            }

            // ---- Online softmax ----
            float rmax0 = NEG_BIG, rmax1 = NEG_BIG;
            #pragma unroll
            for (int nt = 0; nt < 8; ++nt) {
                if (nt < ntmax) {
                    rmax0 = fmaxf(rmax0, fmaxf(sacc[nt][0], sacc[nt][1]));
                    rmax1 = fmaxf(rmax1, fmaxf(sacc[nt][2], sacc[nt][3]));
                }
            }
            rmax0 = fmaxf(rmax0, __shfl_xor_sync(0xffffffffu, rmax0, 1));
            rmax0 = fmaxf(rmax0, __shfl_xor_sync(0xffffffffu, rmax0, 2));
            rmax1 = fmaxf(rmax1, __shfl_xor_sync(0xffffffffu, rmax1, 1));
            rmax1 = fmaxf(rmax1, __shfl_xor_sync(0xffffffffu, rmax1, 2));

            const float mn0 = fmaxf(m0, rmax0);
            const float mn1 = fmaxf(m1, rmax1);
            const float al0 = __expf(m0 - mn0);
            const float al1 = __expf(m1 - mn1);

            float rs0 = 0.f, rs1 = 0.f;
            #pragma unroll
            for (int nt = 0; nt < 8; ++nt) {
                if (nt < ntmax) {
                    const float p00 = __expf(sacc[nt][0] - mn0);
                    const float p01 = __expf(sacc[nt][1] - mn0);
                    const float p10 = __expf(sacc[nt][2] - mn1);
                    const float p11 = __expf(sacc[nt][3] - mn1);
                    rs0 += p00 + p01;
                    rs1 += p10 + p11;
                    uint2 u0; u0.x = tf32_rne(p00); u0.y = tf32_rne(p01);
                    uint2 u1; u1.x = tf32_rne(p10); u1.y = tf32_rne(p11);
                    *(uint2*)(Ps + row0 * QP + nt*8 + qc*2)       = u0;
                    *(uint2*)(Ps + (row0 + 8) * QP + nt*8 + qc*2) = u1;
                }
            }
            rs0 += __shfl_xor_sync(0xffffffffu, rs0, 1);
            rs0 += __shfl_xor_sync(0xffffffffu, rs0, 2);
            rs1 += __shfl_xor_sync(0xffffffffu, rs1, 1);
            rs1 += __shfl_xor_sync(0xffffffffu, rs1, 2);

            l0 = l0 * al0 + rs0;
            l1 = l1 * al1 + rs1;
            m0 = mn0;
            m1 = mn1;

            #pragma unroll
            for (int nt = 0; nt < 8; ++nt) {
                oacc[nt][0] *= al0; oacc[nt][1] *= al0;
                oacc[nt][2] *= al1; oacc[nt][3] *= al1;
            }

            __syncwarp();

            // ---- O += P V ----
            #pragma unroll
            for (int kc = 0; kc < 8; ++kc) {
                if (kc < ntmax) {
                    uint32_t a[4];
                    const uint32_t* pb = (const uint32_t*)(Ps + (w*16 + qr) * QP + kc*8 + qc);
                    a[0] = pb[0];
                    a[1] = pb[8 * QP];
                    a[2] = pb[4];
                    a[3] = pb[8 * QP + 4];
                    #pragma unroll
                    for (int nt = 0; nt < 8; ++nt) {
                        uint32_t bf[2];
                        const uint32_t* vb = (const uint32_t*)(Vs + (kc*8 + qc) * VP + nt*8 + qr);
                        bf[0] = vb[0];
                        bf[1] = vb[4 * VP];
                        mma_tf32(oacc[nt], a, bf);
                    }
                }
            }
        }
    }

    // Epilogue: normalize, tf32-round, scatter into fragment-major y.
    // m = b*2048 + qt*128 + row0(+8) ; c = h*64 + nt*8 + qc*2(+1)
    const float inv0 = 1.0f / l0;
    const float inv1 = 1.0f / l1;
    const int lo = qr * 4 + ((qc * 2) & 3);
    const int hb = (qc >> 1) << 1;
    #pragma unroll
    for (int nt = 0; nt < 8; ++nt) {
        const int ktc = h * 2 + (nt >> 2);
        const int ks  = nt & 3;
        uint32_t* blk = (uint32_t*)(Y + ((size_t)((b * 16 + qt) * 32 + ktc)) * 4096
                                      + (w * 4 + ks) * 128);
        blk[lo * 4 + hb]           = tf32_rne(oacc[nt][0] * inv0);
        blk[(lo + 1) * 4 + hb]     = tf32_rne(oacc[nt][1] * inv0);
        blk[lo * 4 + hb + 1]       = tf32_rne(oacc[nt][2] * inv1);
        blk[(lo + 1) * 4 + hb + 1] = tf32_rne(oacc[nt][3] * inv1);
    }
}

// ---------------------------------------------------------------------------
extern "C" void kernel_launch(void* const* d_in, const int* in_sizes, int n_in,
                              void* d_out, int out_size)
{
    const float* x      = (const float*)d_in[0];
    const float* w_attn = (const float*)d_in[1];
    const float* b_attn = (const float*)d_in[2];
    const float* w_proj = (const float*)d_in[3];
    const float* b_proj = (const float*)d_in[4];
    float* out = (float*)d_out;

    float *yptr = nullptr, *xr = nullptr, *war = nullptr, *wpr = nullptr;
    cudaGetSymbolAddress((void**)&yptr, g_y);
    cudaGetSymbolAddress((void**)&xr,   g_xr);
    cudaGetSymbolAddress((void**)&war,  g_war);
    cudaGetSymbolAddress((void**)&wpr,  g_wpr);

    cudaFuncSetAttribute(gemm_mma_kernel<1>,
                         cudaFuncAttributeMaxDynamicSharedMemorySize, GEMM_SMEM);
    cudaFuncSetAttribute(gemm_mma_kernel<0>,
                         cudaFuncAttributeMaxDynamicSharedMemorySize, GEMM_SMEM);
    cudaFuncSetAttribute(attn_mma_kernel,
                         cudaFuncAttributeMaxDynamicSharedMemorySize, ATTN_SMEM);

    // 0) Pre-pass: permute to fragment-major + tf32 round
    permA_kernel<<<dim3(32, 64), 256>>>(x,      xr,  C_DIM);
    permB_kernel<<<dim3(32, 24), 256>>>(w_attn, war, C_DIM);
    permB_kernel<<<dim3(32,  8), 256>>>(w_proj, wpr, C_DIM);

    // 1) QKV projection; epilogue rounds + scatters Q(scaled)/K/V
    dim3 g1(QKV_N / 128, M_ROWS / 128);   // 24 x 64
    gemm_mma_kernel<1><<<g1, 256, GEMM_SMEM>>>(xr, war, b_attn, nullptr, QKV_N, C_DIM);

    // 2) Causal flash attention -> g_y (fragment-major, tf32)
    dim3 g2(T_ / 128, B_ * H_);           // 16 x 64
    attn_mma_kernel<<<g2, 256, ATTN_SMEM>>>(yptr);

    // 3) Output projection -> d_out (fp32)
    dim3 g3(C_DIM / 128, M_ROWS / 128);   // 8 x 64
    gemm_mma_kernel<0><<<g3, 256, GEMM_SMEM>>>(yptr, wpr, b_proj, out, C_DIM, C_DIM);
}

// round 7
// speedup vs baseline: 1.3332x; 1.3332x over previous
#include <cuda_runtime.h>
#include <cstdint>

// Problem constants
#define B_    4
#define T_    2048
#define C_DIM 1024
#define H_    16
#define D_    64
#define M_ROWS (B_*T_)      // 8192
#define QKV_N  (3*C_DIM)    // 3072
#define NEG_BIG (-3.0e38f)

// Scratch (device globals)
__device__ float g_q[8388608];    // [B,H,T,D]  tf32-prerounded (Q pre-scaled by 1/8)
__device__ float g_k[8388608];
__device__ float g_v[8388608];
__device__ float g_y[8388608];    // fragment-major, tf32-prerounded
__device__ float g_xr[8388608];   // x, fragment-major A-layout, tf32-rounded
__device__ float g_war[3145728];  // w_attn, fragment-major B-layout, tf32-rounded
__device__ float g_wpr[1048576];  // w_proj, fragment-major B-layout, tf32-rounded

// ---------------------------------------------------------------------------
// Helpers
// ---------------------------------------------------------------------------
__device__ __forceinline__ uint32_t cvta_smem(const void* p) {
    uint32_t a;
    asm("{ .reg .u64 t; cvta.to.shared.u64 t, %1; cvt.u32.u64 %0, t; }"
        : "=r"(a) : "l"(p));
    return a;
}
__device__ __forceinline__ void cp_async16(uint32_t dst, const void* src) {
    asm volatile("cp.async.cg.shared.global [%0], [%1], 16;" :: "r"(dst), "l"(src));
}
__device__ __forceinline__ void cp_commit() { asm volatile("cp.async.commit_group;"); }
__device__ __forceinline__ void cp_wait0()  { asm volatile("cp.async.wait_group 0;"); }
__device__ __forceinline__ void cp_wait1()  { asm volatile("cp.async.wait_group 1;"); }
__device__ __forceinline__ void cp_wait2()  { asm volatile("cp.async.wait_group 2;"); }

__device__ __forceinline__ uint32_t tf32_rne(float x) {
    uint32_t y;
    asm("cvt.rna.tf32.f32 %0, %1;" : "=r"(y) : "f"(x));
    return y;
}
__device__ __forceinline__ void mma_tf32(float* d, const uint32_t* a, const uint32_t* b) {
    asm volatile(
        "mma.sync.aligned.m16n8k8.row.col.f32.tf32.tf32.f32 "
        "{%0,%1,%2,%3}, {%4,%5,%6,%7}, {%8,%9}, {%0,%1,%2,%3};"
        : "+f"(d[0]), "+f"(d[1]), "+f"(d[2]), "+f"(d[3])
        : "r"(a[0]), "r"(a[1]), "r"(a[2]), "r"(a[3]), "r"(b[0]), "r"(b[1]));
}

// ---------------------------------------------------------------------------
// Fragment-major permute+round pre-pass (unchanged from round 6)
// ---------------------------------------------------------------------------
__global__ void __launch_bounds__(256) permA_kernel(
    const float* __restrict__ in, float* __restrict__ out, int K)
{
    __shared__ float t[128][33];
    const int kt = blockIdx.x, mb = blockIdx.y;
    const int tid = threadIdx.x;
    const int nkt = K >> 5;
    const float* src = in + (size_t)mb * 128 * K + kt * 32;
    #pragma unroll
    for (int i = 0; i < 4; ++i) {
        const int row = (tid >> 3) + i * 32;
        const int c4  = (tid & 7) * 4;
        float4 v = *(const float4*)(src + (size_t)row * K + c4);
        t[row][c4] = v.x; t[row][c4+1] = v.y; t[row][c4+2] = v.z; t[row][c4+3] = v.w;
    }
    __syncthreads();
    float* dst = out + (size_t)(mb * nkt + kt) * 4096;
    #pragma unroll
    for (int i = 0; i < 4; ++i) {
        const int f = tid + i * 256;
        const int tile = f >> 5, lane = f & 31;
        const int mtile = tile >> 2, ks = tile & 3;
        const int qr = lane >> 2, qc = lane & 3;
        const int m0 = mtile * 16 + qr, k0 = ks * 8 + qc;
        uint4 u;
        u.x = tf32_rne(t[m0][k0]);
        u.y = tf32_rne(t[m0 + 8][k0]);
        u.z = tf32_rne(t[m0][k0 + 4]);
        u.w = tf32_rne(t[m0 + 8][k0 + 4]);
        *(uint4*)(dst + f * 4) = u;
    }
}

__global__ void __launch_bounds__(256) permB_kernel(
    const float* __restrict__ in, float* __restrict__ out, int K)
{
    __shared__ float t[128][33];
    const int kt = blockIdx.x, nb = blockIdx.y;
    const int tid = threadIdx.x;
    const int nkt = K >> 5;
    const float* src = in + (size_t)nb * 128 * K + kt * 32;
    #pragma unroll
    for (int i = 0; i < 4; ++i) {
        const int row = (tid >> 3) + i * 32;
        const int c4  = (tid & 7) * 4;
        float4 v = *(const float4*)(src + (size_t)row * K + c4);
        t[row][c4] = v.x; t[row][c4+1] = v.y; t[row][c4+2] = v.z; t[row][c4+3] = v.w;
    }
    __syncthreads();
    float* dst = out + (size_t)(nb * nkt + kt) * 4096;
    #pragma unroll
    for (int i = 0; i < 4; ++i) {
        const int f = tid + i * 256;
        const int tile = f >> 5, lane = f & 31;
        const int ntile = tile >> 1, kp = tile & 1;
        const int qr = lane >> 2, qc = lane & 3;
        const int n0 = ntile * 8 + qr, k0 = kp * 16 + qc;
        uint4 u;
        u.x = tf32_rne(t[n0][k0]);
        u.y = tf32_rne(t[n0][k0 + 4]);
        u.z = tf32_rne(t[n0][k0 + 8]);
        u.w = tf32_rne(t[n0][k0 + 12]);
        *(uint4*)(dst + f * 4) = u;
    }
}

// ---------------------------------------------------------------------------
// tf32 mma GEMM, fragment-major inputs, 3-stage cp.async (unchanged, round 6)
// ---------------------------------------------------------------------------
#define NSTAGE 3
#define STG_FLOATS 8192
#define GEMM_SMEM (NSTAGE * STG_FLOATS * (int)sizeof(float))   // 98304

template<int MODE>
__global__ void __launch_bounds__(256) gemm_mma_kernel(
    const float* __restrict__ A, const float* __restrict__ W,
    const float* __restrict__ bias, float* __restrict__ out,
    int N, int K)
{
    extern __shared__ float sm[];
    const int tid  = threadIdx.x;
    const int lane = tid & 31;
    const int wid  = tid >> 5;
    const int wm   = wid & 1;
    const int wn   = wid >> 1;
    const int qr   = lane >> 2;
    const int qc   = lane & 3;

    const int nkt = K >> 5;
    const int mb = blockIdx.y, nb = blockIdx.x;
    const float* Ablk = A + (size_t)mb * nkt * 4096;
    const float* Wblk = W + (size_t)nb * nkt * 4096;

    const uint32_t smem_base = cvta_smem(sm);

    float acc[4][4][4];
    #pragma unroll
    for (int i = 0; i < 4; ++i)
        #pragma unroll
        for (int j = 0; j < 4; ++j)
            #pragma unroll
            for (int r = 0; r < 4; ++r) acc[i][j][r] = 0.f;

    #pragma unroll
    for (int s = 0; s < 2; ++s) {
        const uint32_t dst = smem_base + (s * STG_FLOATS + tid * 16) * 4;
        const float* sa = Ablk + (size_t)s * 4096 + tid * 16;
        const float* sb = Wblk + (size_t)s * 4096 + tid * 16;
        #pragma unroll
        for (int j = 0; j < 4; ++j) {
            cp_async16(dst + j * 16,              sa + j * 4);
            cp_async16(dst + 4096 * 4 + j * 16,   sb + j * 4);
        }
        cp_commit();
    }

    for (int kt = 0; kt < nkt; ++kt) {
        __syncthreads();
        if (kt + 2 < nkt) {
            const int s = (kt + 2) % NSTAGE;
            const uint32_t dst = smem_base + (s * STG_FLOATS + tid * 16) * 4;
            const float* sa = Ablk + (size_t)(kt + 2) * 4096 + tid * 16;
            const float* sb = Wblk + (size_t)(kt + 2) * 4096 + tid * 16;
            #pragma unroll
            for (int j = 0; j < 4; ++j) {
                cp_async16(dst + j * 16,            sa + j * 4);
                cp_async16(dst + 4096 * 4 + j * 16, sb + j * 4);
            }
            cp_commit();
            cp_wait2();
        } else if (kt + 1 < nkt) {
            cp_wait1();
        } else {
            cp_wait0();
        }
        __syncthreads();

        const uint32_t* Af = (const uint32_t*)(sm + (kt % NSTAGE) * STG_FLOATS);
        const uint32_t* Bf = Af + 4096;

        uint32_t bq[4][4];
        #pragma unroll
        for (int ks = 0; ks < 4; ++ks) {
            uint32_t af[4][4];
            #pragma unroll
            for (int mt = 0; mt < 4; ++mt) {
                const int mtile = wm * 4 + mt;
                *(uint4*)af[mt] = *(const uint4*)(Af + (mtile * 4 + ks) * 128 + lane * 4);
            }
            if ((ks & 1) == 0) {
                #pragma unroll
                for (int nt = 0; nt < 4; ++nt) {
                    const int ntile = wn * 4 + nt;
                    *(uint4*)bq[nt] = *(const uint4*)(Bf + (ntile * 2 + (ks >> 1)) * 128 + lane * 4);
                }
            }
            #pragma unroll
            for (int mt = 0; mt < 4; ++mt)
                #pragma unroll
                for (int nt = 0; nt < 4; ++nt) {
                    uint32_t bf2[2] = { bq[nt][(ks & 1) * 2], bq[nt][(ks & 1) * 2 + 1] };
                    mma_tf32(acc[mt][nt], af[mt], bf2);
                }
        }
    }

    const int rowBase = mb * 128, colBase = nb * 128;
    #pragma unroll
    for (int nt = 0; nt < 4; ++nt) {
        const int n0 = colBase + wn * 32 + nt * 8 + qc * 2;
        const float b0 = bias[n0], b1 = bias[n0 + 1];
        #pragma unroll
        for (int mt = 0; mt < 4; ++mt) {
            const int m0 = rowBase + wm * 64 + mt * 16 + qr;
            float2 v0 = make_float2(acc[mt][nt][0] + b0, acc[mt][nt][1] + b1);
            float2 v1 = make_float2(acc[mt][nt][2] + b0, acc[mt][nt][3] + b1);
            if (MODE == 0) {
                *(float2*)(out + (size_t)m0 * N + n0)       = v0;
                *(float2*)(out + (size_t)(m0 + 8) * N + n0) = v1;
            } else {
                const int sector = n0 >> 10;          // 0=Q 1=K 2=V
                const int c  = n0 & 1023;
                const int hh = c >> 6, dd = c & 63;
                float* dst = (sector == 0) ? g_q : (sector == 1) ? g_k : g_v;
                const float qs = (sector == 0) ? 0.125f : 1.0f;
                uint2 u0, u1;
                u0.x = tf32_rne(v0.x * qs); u0.y = tf32_rne(v0.y * qs);
                u1.x = tf32_rne(v1.x * qs); u1.y = tf32_rne(v1.y * qs);
                const int bb0 = m0 >> 11, tt0 = m0 & 2047;
                *(uint2*)(dst + ((((size_t)bb0 * H_ + hh) * T_) + tt0) * D_ + dd) = u0;
                const int m1 = m0 + 8;
                const int bb1 = m1 >> 11, tt1 = m1 & 2047;
                *(uint2*)(dst + ((((size_t)bb1 * H_ + hh) * T_) + tt1) * D_ + dd) = u1;
            }
        }
    }
}

// ---------------------------------------------------------------------------
// Tensor-core flash attention, tf32 mma, double-buffered K/V, Q IN REGISTERS.
// Smem: Ps[128][QP] + 2 KV stages = 106,496 B -> 2 CTAs/SM (the round-6 bug
// was 141 KB -> 1 CTA/SM). Q staged once through Ps, then held as qf[8][4].
// ---------------------------------------------------------------------------
#define QP 68
#define VP 72
#define KV_FLOATS (64*QP + 64*VP)
#define ATTN_SMEM ((128*QP + 2*KV_FLOATS) * (int)sizeof(float))  // 106496

__global__ void __launch_bounds__(256, 2) attn_mma_kernel(float* __restrict__ Y)
{
    extern __shared__ float sm[];
    float* Ps = sm;                      // [128][QP]
    float* KV = Ps + 128*QP;             // 2 stages of (Ks[64][QP], Vs[64][VP])

    const int qt  = gridDim.x - 1 - blockIdx.x;
    const int bh  = blockIdx.y;
    const int b   = bh >> 4, h = bh & 15;
    const int tid = threadIdx.x;
    const int lane = tid & 31;
    const int w    = tid >> 5;
    const int qr   = lane >> 2;
    const int qc   = lane & 3;

    const float* Qg = g_q + ((size_t)bh * T_ + qt * 128) * D_;
    const float* Kg = g_k + (size_t)bh * T_ * D_;
    const float* Vg = g_v + (size_t)bh * T_ * D_;

    const uint32_t kv_u = cvta_smem(KV);

    // Prologue: issue KV tile 0 into stage 0 first (deepest latency)
    #pragma unroll
    for (int t = 0; t < 4; ++t) {
        const int slot = tid + t * 256;
        const int r  = slot >> 4;
        const int d0 = (slot & 15) << 2;
        cp_async16(kv_u + (r * QP + d0) * 4, Kg + r * 64 + d0);
        cp_async16(kv_u + (64*QP + r * VP + d0) * 4, Vg + r * 64 + d0);
    }
    cp_commit();

    // Stage Q through Ps (coalesced), pick up fragments into registers, free Ps
    #pragma unroll
    for (int t = 0; t < 8; ++t) {
        const int slot = tid + t * 256;
        const int r  = slot >> 4;
        const int d0 = (slot & 15) << 2;
        *(float4*)(Ps + r * QP + d0) = *(const float4*)(Qg + r * 64 + d0);
    }
    __syncthreads();
    uint32_t qf[8][4];
    {
        const uint32_t* qb = (const uint32_t*)(Ps + (w*16 + qr) * QP);
        #pragma unroll
        for (int kc = 0; kc < 8; ++kc) {
            qf[kc][0] = qb[kc*8 + qc];
            qf[kc][1] = qb[8*QP + kc*8 + qc];
            qf[kc][2] = qb[kc*8 + qc + 4];
            qf[kc][3] = qb[8*QP + kc*8 + qc + 4];
        }
    }

    float m0 = NEG_BIG, m1 = NEG_BIG, l0 = 0.f, l1 = 0.f;
    float oacc[8][4];
    #pragma unroll
    for (int nt = 0; nt < 8; ++nt)
        #pragma unroll
        for (int r = 0; r < 4; ++r) oacc[nt][r] = 0.f;

    const int row0 = w * 16 + qr;
    const int jmax = 2 * qt + 1;

    for (int j = 0; j <= jmax; ++j) {
        __syncthreads();   // tile j-1 consumed; also separates qf pickup from Ps writes

        if (j + 1 <= jmax) {
            const uint32_t stg = kv_u + ((j + 1) & 1) * KV_FLOATS * 4;
            const float* Kgt = Kg + (size_t)(j + 1) * 64 * 64;
            const float* Vgt = Vg + (size_t)(j + 1) * 64 * 64;
            #pragma unroll
            for (int t = 0; t < 4; ++t) {
                const int slot = tid + t * 256;
                const int r  = slot >> 4;
                const int d0 = (slot & 15) << 2;
                cp_async16(stg + (r * QP + d0) * 4, Kgt + r * 64 + d0);
                cp_async16(stg + (64*QP + r * VP + d0) * 4, Vgt + r * 64 + d0);
            }
            cp_commit();
            cp_wait1();
        } else {
            cp_wait0();
        }
        __syncthreads();

        const float* Ks = KV + (j & 1) * KV_FLOATS;
        const float* Vs = Ks + 64*QP;

        int ntmax = 8;
        if (j == 2 * qt) {
            ntmax = 2 * w + 2; if (ntmax > 8) ntmax = 8;
        } else if (j == 2 * qt + 1) {
            ntmax = 2 * w - 6; if (ntmax < 0) ntmax = 0;
        }

        if (ntmax > 0) {
            // ---- S = Q K^T (Q from registers) ----
            float sacc[8][4];
            #pragma unroll
            for (int nt = 0; nt < 8; ++nt)
                #pragma unroll
                for (int r = 0; r < 4; ++r) sacc[nt][r] = 0.f;

            #pragma unroll
            for (int kc = 0; kc < 8; ++kc) {
                #pragma unroll
                for (int nt = 0; nt < 8; ++nt) {
                    if (nt < ntmax) {
                        uint32_t bf[2];
                        const uint32_t* kb = (const uint32_t*)(Ks + (nt*8 + qr) * QP + kc*8 + qc);
                        bf[0] = kb[0];
                        bf[1] = kb[4];
                        mma_tf32(sacc[nt], qf[kc], bf);
                    }
                }
            }

            // ---- Causal mask (diagonal tiles) ----
            if (j >= 2 * qt) {
                const int rel = (j - 2 * qt) * 64;
                #pragma unroll
                for (int nt = 0; nt < 8; ++nt) {
                    if (nt < ntmax) {
                        const int col = rel + nt * 8 + qc * 2;
                        if (col     > row0)     sacc[nt][0] = NEG_BIG;
                        if (col + 1 > row0)     sacc[nt][1] = NEG_BIG;
                        if (col     > row0 + 8) sacc[nt][2] = NEG_BIG;
                        if (col + 1 > row0 + 8) sacc[nt][3] = NEG_BIG;
                    }
                }
            }

            // ---- Online softmax ----
            float rmax0 = NEG_BIG, rmax1 = NEG_BIG;
            #pragma unroll
            for (int nt = 0; nt < 8; ++nt) {
                if (nt < ntmax) {
                    rmax0 = fmaxf(rmax0, fmaxf(sacc[nt][0], sacc[nt][1]));
                    rmax1 = fmaxf(rmax1, fmaxf(sacc[nt][2], sacc[nt][3]));
                }
            }
            rmax0 = fmaxf(rmax0, __shfl_xor_sync(0xffffffffu, rmax0, 1));
            rmax0 = fmaxf(rmax0, __shfl_xor_sync(0xffffffffu, rmax0, 2));
            rmax1 = fmaxf(rmax1, __shfl_xor_sync(0xffffffffu, rmax1, 1));
            rmax1 = fmaxf(rmax1, __shfl_xor_sync(0xffffffffu, rmax1, 2));

            const float mn0 = fmaxf(m0, rmax0);
            const float mn1 = fmaxf(m1, rmax1);
            const float al0 = __expf(m0 - mn0);
            const float al1 = __expf(m1 - mn1);

            float rs0 = 0.f, rs1 = 0.f;
            #pragma unroll
            for (int nt = 0; nt < 8; ++nt) {
                if (nt < ntmax) {
                    const float p00 = __expf(sacc[nt][0] - mn0);
                    const float p01 = __expf(sacc[nt][1] - mn0);
                    const float p10 = __expf(sacc[nt][2] - mn1);
                    const float p11 = __expf(sacc[nt][3] - mn1);
                    rs0 += p00 + p01;
                    rs1 += p10 + p11;
                    uint2 u0; u0.x = tf32_rne(p00); u0.y = tf32_rne(p01);
                    uint2 u1; u1.x = tf32_rne(p10); u1.y = tf32_rne(p11);
                    *(uint2*)(Ps + row0 * QP + nt*8 + qc*2)       = u0;
                    *(uint2*)(Ps + (row0 + 8) * QP + nt*8 + qc*2) = u1;
                }
            }
            rs0 += __shfl_xor_sync(0xffffffffu, rs0, 1);
            rs0 += __shfl_xor_sync(0xffffffffu, rs0, 2);
            rs1 += __shfl_xor_sync(0xffffffffu, rs1, 1);
            rs1 += __shfl_xor_sync(0xffffffffu, rs1, 2);

            l0 = l0 * al0 + rs0;
            l1 = l1 * al1 + rs1;
            m0 = mn0;
            m1 = mn1;

            #pragma unroll
            for (int nt = 0; nt < 8; ++nt) {
                oacc[nt][0] *= al0; oacc[nt][1] *= al0;
                oacc[nt][2] *= al1; oacc[nt][3] *= al1;
            }

            __syncwarp();   // Ps stores visible warp-wide before PV loads

            // ---- O += P V ----
            #pragma unroll
            for (int kc = 0; kc < 8; ++kc) {
                if (kc < ntmax) {
                    uint32_t a[4];
                    const uint32_t* pb = (const uint32_t*)(Ps + (w*16 + qr) * QP + kc*8 + qc);
                    a[0] = pb[0];
                    a[1] = pb[8 * QP];
                    a[2] = pb[4];
                    a[3] = pb[8 * QP + 4];
                    #pragma unroll
                    for (int nt = 0; nt < 8; ++nt) {
                        uint32_t bf[2];
                        const uint32_t* vb = (const uint32_t*)(Vs + (kc*8 + qc) * VP + nt*8 + qr);
                        bf[0] = vb[0];
                        bf[1] = vb[4 * VP];
                        mma_tf32(oacc[nt], a, bf);
                    }
                }
            }
        }
    }

    // Epilogue: normalize, tf32-round, scatter into fragment-major y
    const float inv0 = 1.0f / l0;
    const float inv1 = 1.0f / l1;
    const int lo = qr * 4 + ((qc * 2) & 3);
    const int hb = (qc >> 1) << 1;
    #pragma unroll
    for (int nt = 0; nt < 8; ++nt) {
        const int ktc = h * 2 + (nt >> 2);
        const int ks  = nt & 3;
        uint32_t* blk = (uint32_t*)(Y + ((size_t)((b * 16 + qt) * 32 + ktc)) * 4096
                                      + (w * 4 + ks) * 128);
        blk[lo * 4 + hb]           = tf32_rne(oacc[nt][0] * inv0);
        blk[(lo + 1) * 4 + hb]     = tf32_rne(oacc[nt][1] * inv0);
        blk[lo * 4 + hb + 1]       = tf32_rne(oacc[nt][2] * inv1);
        blk[(lo + 1) * 4 + hb + 1] = tf32_rne(oacc[nt][3] * inv1);
    }
}

// ---------------------------------------------------------------------------
extern "C" void kernel_launch(void* const* d_in, const int* in_sizes, int n_in,
                              void* d_out, int out_size)
{
    const float* x      = (const float*)d_in[0];
    const float* w_attn = (const float*)d_in[1];
    const float* b_attn = (const float*)d_in[2];
    const float* w_proj = (const float*)d_in[3];
    const float* b_proj = (const float*)d_in[4];
    float* out = (float*)d_out;

    float *yptr = nullptr, *xr = nullptr, *war = nullptr, *wpr = nullptr;
    cudaGetSymbolAddress((void**)&yptr, g_y);
    cudaGetSymbolAddress((void**)&xr,   g_xr);
    cudaGetSymbolAddress((void**)&war,  g_war);
    cudaGetSymbolAddress((void**)&wpr,  g_wpr);

    cudaFuncSetAttribute(gemm_mma_kernel<1>,
                         cudaFuncAttributeMaxDynamicSharedMemorySize, GEMM_SMEM);
    cudaFuncSetAttribute(gemm_mma_kernel<0>,
                         cudaFuncAttributeMaxDynamicSharedMemorySize, GEMM_SMEM);
    cudaFuncSetAttribute(attn_mma_kernel,
                         cudaFuncAttributeMaxDynamicSharedMemorySize, ATTN_SMEM);

    // 0) Pre-pass: permute to fragment-major + tf32 round
    permA_kernel<<<dim3(32, 64), 256>>>(x,      xr,  C_DIM);
    permB_kernel<<<dim3(32, 24), 256>>>(w_attn, war, C_DIM);
    permB_kernel<<<dim3(32,  8), 256>>>(w_proj, wpr, C_DIM);

    // 1) QKV projection; epilogue rounds + scatters Q(scaled)/K/V
    dim3 g1(QKV_N / 128, M_ROWS / 128);   // 24 x 64
    gemm_mma_kernel<1><<<g1, 256, GEMM_SMEM>>>(xr, war, b_attn, nullptr, QKV_N, C_DIM);

    // 2) Causal flash attention -> g_y (fragment-major, tf32)
    dim3 g2(T_ / 128, B_ * H_);           // 16 x 64
    attn_mma_kernel<<<g2, 256, ATTN_SMEM>>>(yptr);

    // 3) Output projection -> d_out (fp32)
    dim3 g3(C_DIM / 128, M_ROWS / 128);   // 8 x 64
    gemm_mma_kernel<0><<<g3, 256, GEMM_SMEM>>>(yptr, wpr, b_proj, out, C_DIM, C_DIM);
}